// round 2
// baseline (speedup 1.0000x reference)
#include <cuda_runtime.h>
#include <cstdint>

#define BATCH 16
#define NQ 2048
#define NK 2048
#define DIM 128
#define SCALE 1.153f
#define INV_KEEP (1.0f / 0.7f)

// keep <=> threefry-derived uniform bits < this
// (bits>>9 | 0x3f800000) bitcast - 1.0f < 0.7f  <=>  bits < 0xB3333400
#define KEEP_THRESH 0xB3333400u

// Scratch: scores/probs buffer (268 MB) + bitpacked dropout mask (8 MB)
static __device__ float    g_scores[(size_t)BATCH * NQ * NK];
static __device__ unsigned g_mask[((size_t)BATCH * NQ * NK) / 32];

// ---------------------------------------------------------------------------
// Kernel 1: threefry2x32 dropout mask, bitpacked — PARTITIONABLE semantics
// (jax_threefry_partitionable=True, default in modern JAX):
//   element i: (o0,o1) = threefry2x32(key=(0,42), (hi32(i)=0, lo32(i)=i))
//   bits = o0 ^ o1 ; keep = bits < KEEP_THRESH
// ---------------------------------------------------------------------------
__device__ __forceinline__ unsigned rotl32(unsigned x, int r) {
    return __funnelshift_l(x, x, r);
}

__global__ __launch_bounds__(256) void mask_kernel() {
    unsigned i = blockIdx.x * blockDim.x + threadIdx.x;  // element index (< 2^26)

    const unsigned ks0 = 0u;
    const unsigned ks1 = 42u;
    const unsigned ks2 = 0x1BD11BDAu ^ ks0 ^ ks1;

    unsigned x0 = 0u + ks0;   // counts_hi = 0 for all i < 2^32
    unsigned x1 = i + ks1;    // counts_lo = i

#define TF_ROUND(r) { x0 += x1; x1 = rotl32(x1, (r)); x1 ^= x0; }
    TF_ROUND(13) TF_ROUND(15) TF_ROUND(26) TF_ROUND(6)
    x0 += ks1; x1 += ks2 + 1u;
    TF_ROUND(17) TF_ROUND(29) TF_ROUND(16) TF_ROUND(24)
    x0 += ks2; x1 += ks0 + 2u;
    TF_ROUND(13) TF_ROUND(15) TF_ROUND(26) TF_ROUND(6)
    x0 += ks0; x1 += ks1 + 3u;
    TF_ROUND(17) TF_ROUND(29) TF_ROUND(16) TF_ROUND(24)
    x0 += ks1; x1 += ks2 + 4u;
    TF_ROUND(13) TF_ROUND(15) TF_ROUND(26) TF_ROUND(6)
    x0 += ks2; x1 += ks0 + 5u;
#undef TF_ROUND

    unsigned bits = x0 ^ x1;
    bool keep = (bits < KEEP_THRESH);
    unsigned b = __ballot_sync(0xffffffffu, keep);
    if ((threadIdx.x & 31) == 0) {
        g_mask[i >> 5] = b;
    }
}

// ---------------------------------------------------------------------------
// Kernel 2: S[b,q,k] = SCALE * sum_d x1[b,q,d] * x2[b,k,d]   (NT gemm)
// 128x128 tile, BK=8, 256 threads, 8x8 per-thread micro-tile.
// ---------------------------------------------------------------------------
__global__ __launch_bounds__(256, 2) void gemm1_kernel(const float* __restrict__ x1,
                                                       const float* __restrict__ x2) {
    __shared__ float As[8][132];  // As[d][q]
    __shared__ float Bs[8][132];  // Bs[d][k]

    const int b  = blockIdx.z;
    const int bq = blockIdx.y * 128;
    const int bk = blockIdx.x * 128;
    const float* A  = x1 + (size_t)b * NQ * DIM;
    const float* Bg = x2 + (size_t)b * NK * DIM;
    float* C = g_scores + (size_t)b * NQ * NK;

    const int tid  = threadIdx.x;
    const int tx   = tid & 15;      // 0..15 -> k cols
    const int ty   = tid >> 4;      // 0..15 -> q rows
    const int lrow = tid >> 1;      // 0..127 load row
    const int lc4  = (tid & 1) * 4; // 0 or 4 load col base

    float acc[8][8];
#pragma unroll
    for (int i = 0; i < 8; i++)
#pragma unroll
        for (int j = 0; j < 8; j++) acc[i][j] = 0.0f;

    const float* Aptr = A + (size_t)(bq + lrow) * DIM + lc4;
    const float* Bptr = Bg + (size_t)(bk + lrow) * DIM + lc4;

    for (int d0 = 0; d0 < DIM; d0 += 8) {
        float4 av = *(const float4*)(Aptr + d0);
        float4 bv = *(const float4*)(Bptr + d0);
        __syncthreads();
        As[lc4 + 0][lrow] = av.x; As[lc4 + 1][lrow] = av.y;
        As[lc4 + 2][lrow] = av.z; As[lc4 + 3][lrow] = av.w;
        Bs[lc4 + 0][lrow] = bv.x; Bs[lc4 + 1][lrow] = bv.y;
        Bs[lc4 + 2][lrow] = bv.z; Bs[lc4 + 3][lrow] = bv.w;
        __syncthreads();
#pragma unroll
        for (int d = 0; d < 8; d++) {
            float a[8], bb[8];
#pragma unroll
            for (int j = 0; j < 8; j++) a[j] = As[d][ty * 8 + j];
#pragma unroll
            for (int j = 0; j < 8; j++) bb[j] = Bs[d][tx * 8 + j];
#pragma unroll
            for (int i = 0; i < 8; i++)
#pragma unroll
                for (int j = 0; j < 8; j++) acc[i][j] += a[i] * bb[j];
        }
    }

#pragma unroll
    for (int i = 0; i < 8; i++) {
        float* crow = C + (size_t)(bq + ty * 8 + i) * NK + bk + tx * 8;
        float4 o0 = {acc[i][0] * SCALE, acc[i][1] * SCALE, acc[i][2] * SCALE, acc[i][3] * SCALE};
        float4 o1 = {acc[i][4] * SCALE, acc[i][5] * SCALE, acc[i][6] * SCALE, acc[i][7] * SCALE};
        *(float4*)(crow) = o0;
        *(float4*)(crow + 4) = o1;
    }
}

// ---------------------------------------------------------------------------
// Kernel 3: in-place row softmax + dropout. One block (256 thr) per row.
// probs = exp(s - max)/sum; out = keep ? probs/0.7 : 0
// ---------------------------------------------------------------------------
__global__ __launch_bounds__(256) void softmax_kernel() {
    __shared__ float redm[8];
    __shared__ float reds[8];

    const int row = blockIdx.x;          // 0..BATCH*NQ-1
    float* s = g_scores + (size_t)row * NK;
    const int tid = threadIdx.x;

    float4 v0 = *(const float4*)(s + tid * 8);
    float4 v1 = *(const float4*)(s + tid * 8 + 4);

    float m = fmaxf(fmaxf(fmaxf(v0.x, v0.y), fmaxf(v0.z, v0.w)),
                    fmaxf(fmaxf(v1.x, v1.y), fmaxf(v1.z, v1.w)));
#pragma unroll
    for (int o = 16; o > 0; o >>= 1) m = fmaxf(m, __shfl_xor_sync(0xffffffffu, m, o));
    if ((tid & 31) == 0) redm[tid >> 5] = m;
    __syncthreads();
    float mx = redm[0];
#pragma unroll
    for (int w = 1; w < 8; w++) mx = fmaxf(mx, redm[w]);

    float e[8];
    e[0] = __expf(v0.x - mx); e[1] = __expf(v0.y - mx);
    e[2] = __expf(v0.z - mx); e[3] = __expf(v0.w - mx);
    e[4] = __expf(v1.x - mx); e[5] = __expf(v1.y - mx);
    e[6] = __expf(v1.z - mx); e[7] = __expf(v1.w - mx);

    float sum = 0.0f;
#pragma unroll
    for (int i = 0; i < 8; i++) sum += e[i];
#pragma unroll
    for (int o = 16; o > 0; o >>= 1) sum += __shfl_xor_sync(0xffffffffu, sum, o);
    if ((tid & 31) == 0) reds[tid >> 5] = sum;
    __syncthreads();
    float tot = 0.0f;
#pragma unroll
    for (int w = 0; w < 8; w++) tot += reds[w];
    const float scale = (1.0f / tot) * INV_KEEP;

    // dropout mask bits for this row: word = row*64 + tid/4, bits (tid&3)*8 ..
    unsigned word = g_mask[(size_t)row * (NK / 32) + (tid >> 2)];
    int bbase = (tid & 3) * 8;

    float o[8];
#pragma unroll
    for (int i = 0; i < 8; i++) {
        bool keep = (word >> (bbase + i)) & 1u;
        o[i] = keep ? e[i] * scale : 0.0f;
    }
    float4 w0 = {o[0], o[1], o[2], o[3]};
    float4 w1 = {o[4], o[5], o[6], o[7]};
    *(float4*)(s + tid * 8) = w0;
    *(float4*)(s + tid * 8 + 4) = w1;
}

// ---------------------------------------------------------------------------
// Kernel 4: out[b,q,d] = sum_k P[b,q,k] * x2[b,k,d]   (NN gemm)
// 128x128 tile (full D), BK=8, 256 threads, 8x8 micro-tile.
// ---------------------------------------------------------------------------
__global__ __launch_bounds__(256, 2) void gemm2_kernel(const float* __restrict__ x2,
                                                       float* __restrict__ out) {
    __shared__ float As[8][132];  // As[k][q] (transposed P tile)
    __shared__ float Bs[8][128];  // Bs[k][d] (direct x2 tile)

    const int b  = blockIdx.z;
    const int bq = blockIdx.y * 128;
    const float* A  = g_scores + (size_t)b * NQ * NK;
    const float* Bg = x2 + (size_t)b * NK * DIM;
    float* C = out + (size_t)b * NQ * DIM;

    const int tid  = threadIdx.x;
    const int tx   = tid & 15;
    const int ty   = tid >> 4;
    const int lrow = tid >> 1;
    const int lc4  = (tid & 1) * 4;
    const int brow = tid >> 5;        // 0..7
    const int bcol = (tid & 31) * 4;  // 0..124

    float acc[8][8];
#pragma unroll
    for (int i = 0; i < 8; i++)
#pragma unroll
        for (int j = 0; j < 8; j++) acc[i][j] = 0.0f;

    for (int k0 = 0; k0 < NK; k0 += 8) {
        float4 av = *(const float4*)(A + (size_t)(bq + lrow) * NK + k0 + lc4);
        float4 bv = *(const float4*)(Bg + (size_t)(k0 + brow) * DIM + bcol);
        __syncthreads();
        As[lc4 + 0][lrow] = av.x; As[lc4 + 1][lrow] = av.y;
        As[lc4 + 2][lrow] = av.z; As[lc4 + 3][lrow] = av.w;
        *(float4*)&Bs[brow][bcol] = bv;
        __syncthreads();
#pragma unroll
        for (int k = 0; k < 8; k++) {
            float a[8], bb[8];
#pragma unroll
            for (int j = 0; j < 8; j++) a[j] = As[k][ty * 8 + j];
#pragma unroll
            for (int j = 0; j < 8; j++) bb[j] = Bs[k][tx * 8 + j];
#pragma unroll
            for (int i = 0; i < 8; i++)
#pragma unroll
                for (int j = 0; j < 8; j++) acc[i][j] += a[i] * bb[j];
        }
    }

#pragma unroll
    for (int i = 0; i < 8; i++) {
        float* crow = C + (size_t)(bq + ty * 8 + i) * DIM + tx * 8;
        float4 o0 = {acc[i][0], acc[i][1], acc[i][2], acc[i][3]};
        float4 o1 = {acc[i][4], acc[i][5], acc[i][6], acc[i][7]};
        *(float4*)(crow) = o0;
        *(float4*)(crow + 4) = o1;
    }
}

// ---------------------------------------------------------------------------
extern "C" void kernel_launch(void* const* d_in, const int* in_sizes, int n_in,
                              void* d_out, int out_size) {
    const float* x1 = (const float*)d_in[0];
    const float* x2 = (const float*)d_in[1];
    float* out = (float*)d_out;

    // 1) dropout mask (independent of inputs, must be recomputed every call)
    mask_kernel<<<(1u << 26) / 256, 256>>>();

    // 2) scores = SCALE * x1 @ x2^T
    dim3 g1(NK / 128, NQ / 128, BATCH);
    gemm1_kernel<<<g1, 256>>>(x1, x2);

    // 3) softmax + dropout, in place
    softmax_kernel<<<BATCH * NQ, 256>>>();

    // 4) out = P @ x2
    dim3 g2(1, NQ / 128, BATCH);
    gemm2_kernel<<<g2, 256>>>(x2, out);
}

// round 8
// speedup vs baseline: 1.6554x; 1.6554x over previous
#include <cuda_runtime.h>
#include <cuda_bf16.h>
#include <cstdint>

#define BATCH 16
#define NQ 2048
#define NK 2048
#define DIM 128
#define SCALE 1.153f
#define INV_KEEP (1.0f / 0.7f)
#define KEEP_THRESH 0xB3333400u

// ---------------- scratch (device globals; no allocation allowed) ----------
static __device__ float         g_scores[(size_t)BATCH * NQ * NK];      // 268MB
static __device__ unsigned      g_mask[((size_t)BATCH * NQ * NK) / 32]; // 8MB
static __device__ __nv_bfloat16 g_ph[(size_t)BATCH * NQ * NK];          // 134MB
static __device__ __nv_bfloat16 g_pl[(size_t)BATCH * NQ * NK];          // 134MB
static __device__ __nv_bfloat16 g_x1h[(size_t)BATCH * NQ * DIM];
static __device__ __nv_bfloat16 g_x1l[(size_t)BATCH * NQ * DIM];
static __device__ __nv_bfloat16 g_x2h[(size_t)BATCH * NK * DIM];
static __device__ __nv_bfloat16 g_x2l[(size_t)BATCH * NK * DIM];
static __device__ __nv_bfloat16 g_x2th[(size_t)BATCH * DIM * NK];       // transposed
static __device__ __nv_bfloat16 g_x2tl[(size_t)BATCH * DIM * NK];

// ---------------- warp-mma helpers ------------------------------------------
__device__ __forceinline__ uint32_t smem_u32(const void* p) {
    uint32_t a;
    asm("{ .reg .u64 t; cvta.to.shared.u64 t, %1; cvt.u32.u64 %0, t; }" : "=r"(a) : "l"(p));
    return a;
}

__device__ __forceinline__ void mma16816(float* d, const uint32_t* a, const uint32_t* b) {
    asm volatile(
        "mma.sync.aligned.m16n8k16.row.col.f32.bf16.bf16.f32 "
        "{%0,%1,%2,%3}, {%4,%5,%6,%7}, {%8,%9}, {%0,%1,%2,%3};"
        : "+f"(d[0]), "+f"(d[1]), "+f"(d[2]), "+f"(d[3])
        : "r"(a[0]), "r"(a[1]), "r"(a[2]), "r"(a[3]), "r"(b[0]), "r"(b[1]));
}

__device__ __forceinline__ void ldsm_x4(uint32_t* r, uint32_t addr) {
    asm volatile("ldmatrix.sync.aligned.m8n8.x4.shared.b16 {%0,%1,%2,%3}, [%4];"
                 : "=r"(r[0]), "=r"(r[1]), "=r"(r[2]), "=r"(r[3]) : "r"(addr));
}

// Tile: 128 rows x 128 bf16 cols = 256B/row. 16-byte granules, XOR swizzle.
// byte(row, col8) = row*256 + ((col8>>3 ^ (row&7)) << 4) with col8 = col index (mult of 8)
__device__ __forceinline__ uint32_t tile_addr(uint32_t base, int row, int col) {
    return base + row * 256 + ((((col >> 3) ^ (row & 7)) << 4) | ((col & 7) << 1));
}

// 256-thread cooperative load: gmem row-major [128 x 128] bf16 -> swizzled smem
__device__ __forceinline__ void load_tile(uint32_t dst, const __nv_bfloat16* __restrict__ src,
                                          int ld) {
    const int tid = threadIdx.x;
    uint4 v[8];
#pragma unroll
    for (int i = 0; i < 8; i++) {
        int idx = tid + i * 256;
        int row = idx >> 4;
        int g = idx & 15;
        v[i] = *(const uint4*)(src + (size_t)row * ld + g * 8);
    }
#pragma unroll
    for (int i = 0; i < 8; i++) {
        int idx = tid + i * 256;
        int row = idx >> 4;
        int g = idx & 15;
        uint32_t a = dst + row * 256 + ((g ^ (row & 7)) << 4);
        asm volatile("st.shared.v4.b32 [%0], {%1,%2,%3,%4};"
                     :: "r"(a), "r"(v[i].x), "r"(v[i].y), "r"(v[i].z), "r"(v[i].w));
    }
}

#define TILE_BYTES 32768
#define SM_AH 0
#define SM_AL (TILE_BYTES)
#define SM_BH (2 * TILE_BYTES)
#define SM_BL (3 * TILE_BYTES)
#define SMEM_BYTES (4 * TILE_BYTES)

// one pass of 128x128x128 warp-mma: C += A(desc ah) * B(desc bh)^T-ish
// warp tile 64x32 at (wm*64, wn*32); acc[4 m-frags][4 n-frags][4]
__device__ __forceinline__ void mma_pass(float acc[4][4][4], uint32_t A, uint32_t B,
                                         int wm, int wn, int lane) {
    const int arow = wm * 64 + (lane & 15);
    const int acol_lane = (lane >> 4) * 8;
    const int brow = wn * 32 + ((lane >> 4) << 3) + (lane & 7);
    const int bcol_lane = ((lane >> 3) & 1) * 8;
#pragma unroll
    for (int ks = 0; ks < 8; ks++) {
        const int k0 = ks * 16;
        uint32_t af[4][4];
#pragma unroll
        for (int mi = 0; mi < 4; mi++)
            ldsm_x4(af[mi], tile_addr(A, arow + mi * 16, k0 + acol_lane));
        uint32_t bf[2][4];
#pragma unroll
        for (int nb = 0; nb < 2; nb++)
            ldsm_x4(bf[nb], tile_addr(B, brow + nb * 16, k0 + bcol_lane));
#pragma unroll
        for (int mi = 0; mi < 4; mi++) {
#pragma unroll
            for (int nj = 0; nj < 4; nj++)
                mma16816(acc[mi][nj], af[mi], &bf[nj >> 1][(nj & 1) * 2]);
        }
    }
}

// ---------------------------------------------------------------------------
// threefry2x32 partitionable dropout mask (verified exact)
// ---------------------------------------------------------------------------
__device__ __forceinline__ unsigned rotl32(unsigned x, int r) { return __funnelshift_l(x, x, r); }

__global__ __launch_bounds__(256) void mask_kernel() {
    unsigned i = blockIdx.x * blockDim.x + threadIdx.x;
    const unsigned ks0 = 0u, ks1 = 42u, ks2 = 0x1BD11BDAu ^ ks0 ^ ks1;
    unsigned x0 = ks0, x1 = i + ks1;
#define TF_ROUND(r) { x0 += x1; x1 = rotl32(x1, (r)); x1 ^= x0; }
    TF_ROUND(13) TF_ROUND(15) TF_ROUND(26) TF_ROUND(6)
    x0 += ks1; x1 += ks2 + 1u;
    TF_ROUND(17) TF_ROUND(29) TF_ROUND(16) TF_ROUND(24)
    x0 += ks2; x1 += ks0 + 2u;
    TF_ROUND(13) TF_ROUND(15) TF_ROUND(26) TF_ROUND(6)
    x0 += ks0; x1 += ks1 + 3u;
    TF_ROUND(17) TF_ROUND(29) TF_ROUND(16) TF_ROUND(24)
    x0 += ks1; x1 += ks2 + 4u;
    TF_ROUND(13) TF_ROUND(15) TF_ROUND(26) TF_ROUND(6)
    x0 += ks2; x1 += ks0 + 5u;
#undef TF_ROUND
    unsigned b = __ballot_sync(0xffffffffu, (x0 ^ x1) < KEEP_THRESH);
    if ((threadIdx.x & 31) == 0) g_mask[i >> 5] = b;
}

// ---------------------------------------------------------------------------
// split fp32 -> bf16 hi/lo for x1, x2
// ---------------------------------------------------------------------------
__global__ __launch_bounds__(256) void split_kernel(const float* __restrict__ x1,
                                                    const float* __restrict__ x2) {
    size_t i = (size_t)blockIdx.x * blockDim.x + threadIdx.x;
    float a = x1[i];
    __nv_bfloat16 h = __float2bfloat16(a);
    g_x1h[i] = h;
    g_x1l[i] = __float2bfloat16(a - __bfloat162float(h));
    float c = x2[i];
    __nv_bfloat16 h2 = __float2bfloat16(c);
    g_x2h[i] = h2;
    g_x2l[i] = __float2bfloat16(c - __bfloat162float(h2));
}

// transpose x2 [B][NK][DIM] -> x2t [B][DIM][NK], bf16 hi/lo
__global__ __launch_bounds__(1024) void transpose_kernel(const float* __restrict__ x2) {
    __shared__ __nv_bfloat16 th[32][33];
    __shared__ __nv_bfloat16 tl[32][33];
    const int b = blockIdx.z;
    const int k0 = blockIdx.x * 32;
    const int d0 = blockIdx.y * 32;
    const int tx = threadIdx.x & 31;
    const int ty = threadIdx.x >> 5;
    float v = x2[(size_t)b * NK * DIM + (size_t)(k0 + ty) * DIM + d0 + tx];
    __nv_bfloat16 h = __float2bfloat16(v);
    th[tx][ty] = h;
    tl[tx][ty] = __float2bfloat16(v - __bfloat162float(h));
    __syncthreads();
    size_t o = (size_t)b * DIM * NK + (size_t)(d0 + ty) * NK + k0 + tx;
    g_x2th[o] = th[ty][tx];
    g_x2tl[o] = tl[ty][tx];
}

// ---------------------------------------------------------------------------
// GEMM1: scores = SCALE * x1 @ x2^T, warp-mma hi/lo split
// grid (k-tile=16, q-tile=16, batch=16), 256 threads (8 warps, 2x4)
// ---------------------------------------------------------------------------
__global__ __launch_bounds__(256, 1) void gemm1_tc() {
    extern __shared__ char smem[];
    uint32_t base = smem_u32(smem);
    const int tid = threadIdx.x;
    const int wid = tid >> 5;
    const int lane = tid & 31;
    const int wm = wid & 1;
    const int wn = wid >> 1;

    const int b = blockIdx.z;
    const int bq = blockIdx.y * 128;
    const int bk = blockIdx.x * 128;
    const size_t aoff = (size_t)b * NQ * DIM + (size_t)bq * DIM;
    const size_t boff = (size_t)b * NK * DIM + (size_t)bk * DIM;
    load_tile(base + SM_AH, g_x1h + aoff, DIM);
    load_tile(base + SM_AL, g_x1l + aoff, DIM);
    load_tile(base + SM_BH, g_x2h + boff, DIM);
    load_tile(base + SM_BL, g_x2l + boff, DIM);
    __syncthreads();

    float acc[4][4][4];
#pragma unroll
    for (int i = 0; i < 4; i++)
#pragma unroll
        for (int j = 0; j < 4; j++)
#pragma unroll
            for (int r = 0; r < 4; r++) acc[i][j][r] = 0.0f;

    mma_pass(acc, base + SM_AH, base + SM_BH, wm, wn, lane);
    mma_pass(acc, base + SM_AH, base + SM_BL, wm, wn, lane);
    mma_pass(acc, base + SM_AL, base + SM_BH, wm, wn, lane);

    // epilogue: scale + store fp32 scores
    float* C = g_scores + (size_t)b * NQ * NK + (size_t)bq * NK + bk;
    const int r0 = wm * 64 + (lane >> 2);
    const int c0 = wn * 32 + (lane & 3) * 2;
#pragma unroll
    for (int mi = 0; mi < 4; mi++) {
#pragma unroll
        for (int nj = 0; nj < 4; nj++) {
            float* p0 = C + (size_t)(r0 + mi * 16) * NK + c0 + nj * 8;
            float* p1 = C + (size_t)(r0 + mi * 16 + 8) * NK + c0 + nj * 8;
            *(float2*)p0 = make_float2(acc[mi][nj][0] * SCALE, acc[mi][nj][1] * SCALE);
            *(float2*)p1 = make_float2(acc[mi][nj][2] * SCALE, acc[mi][nj][3] * SCALE);
        }
    }
}

// ---------------------------------------------------------------------------
// softmax + dropout: scores -> P as bf16 hi/lo
// ---------------------------------------------------------------------------
__global__ __launch_bounds__(256) void softmax_kernel() {
    __shared__ float redm[8];
    __shared__ float reds[8];
    const int row = blockIdx.x;
    const float* s = g_scores + (size_t)row * NK;
    const int tid = threadIdx.x;

    float4 v0 = *(const float4*)(s + tid * 8);
    float4 v1 = *(const float4*)(s + tid * 8 + 4);

    float m = fmaxf(fmaxf(fmaxf(v0.x, v0.y), fmaxf(v0.z, v0.w)),
                    fmaxf(fmaxf(v1.x, v1.y), fmaxf(v1.z, v1.w)));
#pragma unroll
    for (int o = 16; o > 0; o >>= 1) m = fmaxf(m, __shfl_xor_sync(0xffffffffu, m, o));
    if ((tid & 31) == 0) redm[tid >> 5] = m;
    __syncthreads();
    float mx = redm[0];
#pragma unroll
    for (int w = 1; w < 8; w++) mx = fmaxf(mx, redm[w]);

    float e[8];
    e[0] = __expf(v0.x - mx); e[1] = __expf(v0.y - mx);
    e[2] = __expf(v0.z - mx); e[3] = __expf(v0.w - mx);
    e[4] = __expf(v1.x - mx); e[5] = __expf(v1.y - mx);
    e[6] = __expf(v1.z - mx); e[7] = __expf(v1.w - mx);

    float sum = 0.0f;
#pragma unroll
    for (int i = 0; i < 8; i++) sum += e[i];
#pragma unroll
    for (int o = 16; o > 0; o >>= 1) sum += __shfl_xor_sync(0xffffffffu, sum, o);
    if ((tid & 31) == 0) reds[tid >> 5] = sum;
    __syncthreads();
    float tot = 0.0f;
#pragma unroll
    for (int w = 0; w < 8; w++) tot += reds[w];
    const float scale = (1.0f / tot) * INV_KEEP;

    unsigned word = g_mask[(size_t)row * (NK / 32) + (tid >> 2)];
    int bbase = (tid & 3) * 8;

    uint32_t hw[4], lw[4];
#pragma unroll
    for (int j = 0; j < 4; j++) {
        float a = ((word >> (bbase + 2 * j)) & 1u) ? e[2 * j] * scale : 0.0f;
        float c = ((word >> (bbase + 2 * j + 1)) & 1u) ? e[2 * j + 1] * scale : 0.0f;
        __nv_bfloat16 ha = __float2bfloat16(a), hc = __float2bfloat16(c);
        __nv_bfloat16 la = __float2bfloat16(a - __bfloat162float(ha));
        __nv_bfloat16 lc = __float2bfloat16(c - __bfloat162float(hc));
        hw[j] = (uint32_t)__bfloat16_as_ushort(ha) | ((uint32_t)__bfloat16_as_ushort(hc) << 16);
        lw[j] = (uint32_t)__bfloat16_as_ushort(la) | ((uint32_t)__bfloat16_as_ushort(lc) << 16);
    }
    size_t o = (size_t)row * NK + tid * 8;
    *(uint4*)(g_ph + o) = make_uint4(hw[0], hw[1], hw[2], hw[3]);
    *(uint4*)(g_pl + o) = make_uint4(lw[0], lw[1], lw[2], lw[3]);
}

// ---------------------------------------------------------------------------
// GEMM2: out = P @ x2, warp-mma, K=2048 in 16 chunks
// grid (q-tile=16, batch=16), 256 threads
// ---------------------------------------------------------------------------
__global__ __launch_bounds__(256, 1) void gemm2_tc(float* __restrict__ out) {
    extern __shared__ char smem[];
    uint32_t base = smem_u32(smem);
    const int tid = threadIdx.x;
    const int wid = tid >> 5;
    const int lane = tid & 31;
    const int wm = wid & 1;
    const int wn = wid >> 1;

    const int b = blockIdx.y;
    const int bq = blockIdx.x * 128;
    const __nv_bfloat16* ph = g_ph + ((size_t)b * NQ + bq) * NK;
    const __nv_bfloat16* pl = g_pl + ((size_t)b * NQ + bq) * NK;
    const __nv_bfloat16* vh = g_x2th + (size_t)b * DIM * NK;
    const __nv_bfloat16* vl = g_x2tl + (size_t)b * DIM * NK;

    float acc[4][4][4];
#pragma unroll
    for (int i = 0; i < 4; i++)
#pragma unroll
        for (int j = 0; j < 4; j++)
#pragma unroll
            for (int r = 0; r < 4; r++) acc[i][j][r] = 0.0f;

    for (int t = 0; t < 16; t++) {
        const int k0 = t * 128;
        load_tile(base + SM_AH, ph + k0, NK);
        load_tile(base + SM_AL, pl + k0, NK);
        load_tile(base + SM_BH, vh + k0, NK);
        load_tile(base + SM_BL, vl + k0, NK);
        __syncthreads();

        mma_pass(acc, base + SM_AH, base + SM_BH, wm, wn, lane);
        mma_pass(acc, base + SM_AH, base + SM_BL, wm, wn, lane);
        mma_pass(acc, base + SM_AL, base + SM_BH, wm, wn, lane);
        __syncthreads();
    }

    float* C = out + (size_t)b * NQ * DIM + (size_t)bq * DIM;
    const int r0 = wm * 64 + (lane >> 2);
    const int c0 = wn * 32 + (lane & 3) * 2;
#pragma unroll
    for (int mi = 0; mi < 4; mi++) {
#pragma unroll
        for (int nj = 0; nj < 4; nj++) {
            float* p0 = C + (size_t)(r0 + mi * 16) * DIM + c0 + nj * 8;
            float* p1 = C + (size_t)(r0 + mi * 16 + 8) * DIM + c0 + nj * 8;
            *(float2*)p0 = make_float2(acc[mi][nj][0], acc[mi][nj][1]);
            *(float2*)p1 = make_float2(acc[mi][nj][2], acc[mi][nj][3]);
        }
    }
}

// ---------------------------------------------------------------------------
extern "C" void kernel_launch(void* const* d_in, const int* in_sizes, int n_in,
                              void* d_out, int out_size) {
    const float* x1 = (const float*)d_in[0];
    const float* x2 = (const float*)d_in[1];
    float* out = (float*)d_out;

    static int configured = 0;
    if (!configured) {
        cudaFuncSetAttribute(gemm1_tc, cudaFuncAttributeMaxDynamicSharedMemorySize, SMEM_BYTES);
        cudaFuncSetAttribute(gemm2_tc, cudaFuncAttributeMaxDynamicSharedMemorySize, SMEM_BYTES);
        configured = 1;
    }

    mask_kernel<<<(1u << 26) / 256, 256>>>();
    split_kernel<<<(BATCH * NQ * DIM) / 256, 256>>>(x1, x2);
    transpose_kernel<<<dim3(NK / 32, DIM / 32, BATCH), 1024>>>(x2);

    gemm1_tc<<<dim3(16, 16, BATCH), 256, SMEM_BYTES>>>();
    softmax_kernel<<<BATCH * NQ, 256>>>();
    gemm2_tc<<<dim3(16, BATCH), 256, SMEM_BYTES>>>(out);
}

// round 10
// speedup vs baseline: 2.5311x; 1.5290x over previous
#include <cuda_runtime.h>
#include <cuda_bf16.h>
#include <cstdint>

#define BATCH 16
#define NQ 2048
#define NK 2048
#define DIM 128
#define SCALE 1.153f
#define INV_KEEP (1.0f / 0.7f)
#define KEEP_THRESH 0xB3333400u

// ---------------- scratch ---------------------------------------------------
static __device__ unsigned      g_mask[((size_t)BATCH * NQ * NK) / 32]; // 8MB
static __device__ __nv_bfloat16 g_x1h[(size_t)BATCH * NQ * DIM];
static __device__ __nv_bfloat16 g_x1l[(size_t)BATCH * NQ * DIM];
static __device__ __nv_bfloat16 g_x2h[(size_t)BATCH * NK * DIM];
static __device__ __nv_bfloat16 g_x2l[(size_t)BATCH * NK * DIM];

// ---------------- helpers ---------------------------------------------------
__device__ __forceinline__ uint32_t smem_u32(const void* p) {
    uint32_t a;
    asm("{ .reg .u64 t; cvta.to.shared.u64 t, %1; cvt.u32.u64 %0, t; }" : "=r"(a) : "l"(p));
    return a;
}
__device__ __forceinline__ void mma16816(float* d, const uint32_t* a, const uint32_t* b) {
    asm volatile(
        "mma.sync.aligned.m16n8k16.row.col.f32.bf16.bf16.f32 "
        "{%0,%1,%2,%3}, {%4,%5,%6,%7}, {%8,%9}, {%0,%1,%2,%3};"
        : "+f"(d[0]), "+f"(d[1]), "+f"(d[2]), "+f"(d[3])
        : "r"(a[0]), "r"(a[1]), "r"(a[2]), "r"(a[3]), "r"(b[0]), "r"(b[1]));
}
__device__ __forceinline__ void ldsm_x4(uint32_t* r, uint32_t addr) {
    asm volatile("ldmatrix.sync.aligned.m8n8.x4.shared.b16 {%0,%1,%2,%3}, [%4];"
                 : "=r"(r[0]), "=r"(r[1]), "=r"(r[2]), "=r"(r[3]) : "r"(addr));
}
__device__ __forceinline__ void ldsm_x4_t(uint32_t* r, uint32_t addr) {
    asm volatile("ldmatrix.sync.aligned.m8n8.x4.trans.shared.b16 {%0,%1,%2,%3}, [%4];"
                 : "=r"(r[0]), "=r"(r[1]), "=r"(r[2]), "=r"(r[3]) : "r"(addr));
}
// pack two fp32 -> bf16x2 (lo -> low half, hi -> high half), round-to-nearest
__device__ __forceinline__ uint32_t pack_bf16(float lo, float hi) {
    uint32_t r;
    asm("cvt.rn.bf16x2.f32 %0, %1, %2;" : "=r"(r) : "f"(hi), "f"(lo));
    return r;
}
__device__ __forceinline__ void cp_async16(uint32_t dst, const void* src) {
    asm volatile("cp.async.cg.shared.global [%0], [%1], 16;" :: "r"(dst), "l"(src));
}
#define CP_COMMIT() asm volatile("cp.async.commit_group;" ::: "memory")

// 128x128 bf16 tile: 256B/row, XOR swizzle on 16B granules
__device__ __forceinline__ uint32_t tile_addr(uint32_t base, int row, int col) {
    return base + row * 256 + ((((col >> 3) ^ (row & 7)) << 4));
}
__device__ __forceinline__ void load_tile(uint32_t dst, const __nv_bfloat16* __restrict__ src,
                                          int ld) {
    const int tid = threadIdx.x;
    uint4 v[8];
#pragma unroll
    for (int i = 0; i < 8; i++) {
        int idx = tid + i * 256;
        int row = idx >> 4, g = idx & 15;
        v[i] = *(const uint4*)(src + (size_t)row * ld + g * 8);
    }
#pragma unroll
    for (int i = 0; i < 8; i++) {
        int idx = tid + i * 256;
        int row = idx >> 4, g = idx & 15;
        uint32_t a = dst + row * 256 + ((g ^ (row & 7)) << 4);
        asm volatile("st.shared.v4.b32 [%0], {%1,%2,%3,%4};"
                     :: "r"(a), "r"(v[i].x), "r"(v[i].y), "r"(v[i].z), "r"(v[i].w));
    }
}
__device__ __forceinline__ void cp_tile(uint32_t dst, const __nv_bfloat16* __restrict__ src,
                                        int ld) {
    const int tid = threadIdx.x;
#pragma unroll
    for (int i = 0; i < 8; i++) {
        int idx = tid + i * 256;
        int row = idx >> 4, g = idx & 15;
        cp_async16(dst + row * 256 + ((g ^ (row & 7)) << 4), src + (size_t)row * ld + g * 8);
    }
}

#define SM_X1H 0
#define SM_X1L 32768
#define SM_X2(buf) (65536 + (buf) * 65536)  // x2h at +0, x2l at +32768
#define SMEM_BYTES (65536 + 2 * 65536)       // 192KB

// ---------------------------------------------------------------------------
// threefry2x32 partitionable dropout mask (verified exact)
// ---------------------------------------------------------------------------
__device__ __forceinline__ unsigned rotl32(unsigned x, int r) { return __funnelshift_l(x, x, r); }

__global__ __launch_bounds__(256) void mask_kernel() {
    unsigned i = blockIdx.x * blockDim.x + threadIdx.x;
    const unsigned ks0 = 0u, ks1 = 42u, ks2 = 0x1BD11BDAu ^ ks0 ^ ks1;
    unsigned x0 = ks0, x1 = i + ks1;
#define TF_ROUND(r) { x0 += x1; x1 = rotl32(x1, (r)); x1 ^= x0; }
    TF_ROUND(13) TF_ROUND(15) TF_ROUND(26) TF_ROUND(6)
    x0 += ks1; x1 += ks2 + 1u;
    TF_ROUND(17) TF_ROUND(29) TF_ROUND(16) TF_ROUND(24)
    x0 += ks2; x1 += ks0 + 2u;
    TF_ROUND(13) TF_ROUND(15) TF_ROUND(26) TF_ROUND(6)
    x0 += ks0; x1 += ks1 + 3u;
    TF_ROUND(17) TF_ROUND(29) TF_ROUND(16) TF_ROUND(24)
    x0 += ks1; x1 += ks2 + 4u;
    TF_ROUND(13) TF_ROUND(15) TF_ROUND(26) TF_ROUND(6)
    x0 += ks2; x1 += ks0 + 5u;
#undef TF_ROUND
    unsigned b = __ballot_sync(0xffffffffu, (x0 ^ x1) < KEEP_THRESH);
    if ((threadIdx.x & 31) == 0) g_mask[i >> 5] = b;
}

// ---------------------------------------------------------------------------
// split fp32 -> bf16 hi/lo for x1, x2
// ---------------------------------------------------------------------------
__global__ __launch_bounds__(256) void split_kernel(const float* __restrict__ x1,
                                                    const float* __restrict__ x2) {
    size_t i = (size_t)blockIdx.x * blockDim.x + threadIdx.x;
    float a = x1[i];
    __nv_bfloat16 h = __float2bfloat16(a);
    g_x1h[i] = h;
    g_x1l[i] = __float2bfloat16(a - __bfloat162float(h));
    float c = x2[i];
    __nv_bfloat16 h2 = __float2bfloat16(c);
    g_x2h[i] = h2;
    g_x2l[i] = __float2bfloat16(c - __bfloat162float(h2));
}

// ---------------------------------------------------------------------------
// Fused attention: S = SCALE*x1 x2^T -> online softmax -> dropout -> O = P x2
// grid (q-tile=16, batch=16), 256 threads (8 warps), warp owns 16 q rows.
// ---------------------------------------------------------------------------
__global__ __launch_bounds__(256, 1) void fused_attn(float* __restrict__ out) {
    extern __shared__ char smem[];
    uint32_t base = smem_u32(smem);
    const int tid = threadIdx.x;
    const int w = tid >> 5;
    const int lane = tid & 31;
    const int b = blockIdx.y;
    const int bq = blockIdx.x * 128;

    // x1 q-tile (hi/lo) resident for whole kernel
    const size_t aoff = ((size_t)b * NQ + bq) * DIM;
    load_tile(base + SM_X1H, g_x1h + aoff, DIM);
    load_tile(base + SM_X1L, g_x1l + aoff, DIM);

    const __nv_bfloat16* x2h = g_x2h + (size_t)b * NK * DIM;
    const __nv_bfloat16* x2l = g_x2l + (size_t)b * NK * DIM;
    // prefetch k-tile 0
    cp_tile(base + SM_X2(0), x2h, DIM);
    cp_tile(base + SM_X2(0) + 32768, x2l, DIM);
    CP_COMMIT();

    // fragment geometry
    const int arow = w * 16 + (lane & 15);
    const int acol = (lane >> 4) * 8;
    const int bro = ((lane >> 4) << 3) + (lane & 7);
    const int bco = ((lane >> 3) & 1) * 8;
    const int vro = ((lane >> 3) & 1) * 8 + (lane & 7);
    const int vco = (lane >> 4) * 8;
    const int qr = (lane & 3) * 2;  // col offset within n8 frag

    // softmax state + output accumulator
    float m0 = -INFINITY, m1 = -INFINITY, l0 = 0.0f, l1 = 0.0f;
    float O[16][4];
#pragma unroll
    for (int i = 0; i < 16; i++)
#pragma unroll
        for (int j = 0; j < 4; j++) O[i][j] = 0.0f;

    // dropout mask word bases (words of 32 bits; 64 words per row)
    const int row_g0 = b * NQ + bq + w * 16 + (lane >> 2);
    const size_t mrow0 = (size_t)row_g0 * 64;
    const size_t mrow1 = mrow0 + 8 * 64;

    for (int t = 0; t < 16; t++) {
        if (t + 1 < 16) {
            cp_tile(base + SM_X2((t + 1) & 1), x2h + (size_t)(t + 1) * 128 * DIM, DIM);
            cp_tile(base + SM_X2((t + 1) & 1) + 32768, x2l + (size_t)(t + 1) * 128 * DIM, DIM);
            CP_COMMIT();
            asm volatile("cp.async.wait_group 1;" ::: "memory");
        } else {
            asm volatile("cp.async.wait_group 0;" ::: "memory");
        }
        __syncthreads();
        const uint32_t X2H = base + SM_X2(t & 1);
        const uint32_t X2L = X2H + 32768;

        // ---- S-pass: acc = x1 . x2^T (hi*hi + hi*lo + lo*hi) ----
        float acc[16][4];
#pragma unroll
        for (int i = 0; i < 16; i++)
#pragma unroll
            for (int j = 0; j < 4; j++) acc[i][j] = 0.0f;

#pragma unroll
        for (int ks = 0; ks < 8; ks++) {
            uint32_t ah[4], al[4];
            ldsm_x4(ah, tile_addr(base + SM_X1H, arow, ks * 16 + acol));
            ldsm_x4(al, tile_addr(base + SM_X1L, arow, ks * 16 + acol));
#pragma unroll
            for (int nb = 0; nb < 8; nb++) {
                uint32_t bh[4], bl[4];
                ldsm_x4(bh, tile_addr(X2H, nb * 16 + bro, ks * 16 + bco));
                ldsm_x4(bl, tile_addr(X2L, nb * 16 + bro, ks * 16 + bco));
                mma16816(acc[2 * nb], ah, bh);
                mma16816(acc[2 * nb + 1], ah, bh + 2);
                mma16816(acc[2 * nb], ah, bl);
                mma16816(acc[2 * nb + 1], ah, bl + 2);
                mma16816(acc[2 * nb], al, bh);
                mma16816(acc[2 * nb + 1], al, bh + 2);
            }
        }

        // ---- online softmax + dropout + bf16 hi/lo pack ----
        float tm0 = -INFINITY, tm1 = -INFINITY;
#pragma unroll
        for (int nf = 0; nf < 16; nf++) {
            acc[nf][0] *= SCALE; acc[nf][1] *= SCALE;
            acc[nf][2] *= SCALE; acc[nf][3] *= SCALE;
            tm0 = fmaxf(tm0, fmaxf(acc[nf][0], acc[nf][1]));
            tm1 = fmaxf(tm1, fmaxf(acc[nf][2], acc[nf][3]));
        }
        tm0 = fmaxf(tm0, __shfl_xor_sync(0xffffffffu, tm0, 1));
        tm0 = fmaxf(tm0, __shfl_xor_sync(0xffffffffu, tm0, 2));
        tm1 = fmaxf(tm1, __shfl_xor_sync(0xffffffffu, tm1, 1));
        tm1 = fmaxf(tm1, __shfl_xor_sync(0xffffffffu, tm1, 2));
        const float nm0 = fmaxf(m0, tm0);
        const float nm1 = fmaxf(m1, tm1);
        const float f0 = __expf(m0 - nm0);
        const float f1 = __expf(m1 - nm1);
        m0 = nm0; m1 = nm1;
        l0 *= f0; l1 *= f1;
#pragma unroll
        for (int nf = 0; nf < 16; nf++) {
            O[nf][0] *= f0; O[nf][1] *= f0;
            O[nf][2] *= f1; O[nf][3] *= f1;
        }

        unsigned um0[4], um1[4];
#pragma unroll
        for (int j = 0; j < 4; j++) {
            um0[j] = g_mask[mrow0 + t * 4 + j];
            um1[j] = g_mask[mrow1 + t * 4 + j];
        }

        uint32_t PH0[16], PH1[16], PL0[16], PL1[16];
#pragma unroll
        for (int nf = 0; nf < 16; nf++) {
            float e0 = __expf(acc[nf][0] - m0);
            float e1 = __expf(acc[nf][1] - m0);
            float e2 = __expf(acc[nf][2] - m1);
            float e3 = __expf(acc[nf][3] - m1);
            l0 += e0 + e1;
            l1 += e2 + e3;
            const int sh = (nf & 3) * 8 + qr;
            unsigned w0 = um0[nf >> 2] >> sh;
            unsigned w1 = um1[nf >> 2] >> sh;
            float p0 = (w0 & 1u) ? e0 : 0.0f;
            float p1 = (w0 & 2u) ? e1 : 0.0f;
            float p2 = (w1 & 1u) ? e2 : 0.0f;
            float p3 = (w1 & 2u) ? e3 : 0.0f;
            uint32_t h0 = pack_bf16(p0, p1);
            uint32_t h1 = pack_bf16(p2, p3);
            PH0[nf] = h0;
            PH1[nf] = h1;
            PL0[nf] = pack_bf16(p0 - __uint_as_float(h0 << 16),
                                p1 - __uint_as_float(h0 & 0xffff0000u));
            PL1[nf] = pack_bf16(p2 - __uint_as_float(h1 << 16),
                                p3 - __uint_as_float(h1 & 0xffff0000u));
        }

        // ---- PV-pass: O += P . V  (Ph*Vh + Ph*Vl + Pl*Vh) ----
#pragma unroll
        for (int ks = 0; ks < 8; ks++) {
            uint32_t ah[4] = {PH0[2 * ks], PH1[2 * ks], PH0[2 * ks + 1], PH1[2 * ks + 1]};
            uint32_t al[4] = {PL0[2 * ks], PL1[2 * ks], PL0[2 * ks + 1], PL1[2 * ks + 1]};
#pragma unroll
            for (int nb = 0; nb < 8; nb++) {
                uint32_t vh[4], vl[4];
                ldsm_x4_t(vh, tile_addr(X2H, ks * 16 + vro, nb * 16 + vco));
                ldsm_x4_t(vl, tile_addr(X2L, ks * 16 + vro, nb * 16 + vco));
                mma16816(O[2 * nb], ah, vh);
                mma16816(O[2 * nb + 1], ah, vh + 2);
                mma16816(O[2 * nb], ah, vl);
                mma16816(O[2 * nb + 1], ah, vl + 2);
                mma16816(O[2 * nb], al, vh);
                mma16816(O[2 * nb + 1], al, vh + 2);
            }
        }
        __syncthreads();  // all warps done with this x2 buffer before next prefetch reuses it
    }

    // ---- epilogue: O / (l * 0.7) ----
    l0 += __shfl_xor_sync(0xffffffffu, l0, 1);
    l0 += __shfl_xor_sync(0xffffffffu, l0, 2);
    l1 += __shfl_xor_sync(0xffffffffu, l1, 1);
    l1 += __shfl_xor_sync(0xffffffffu, l1, 2);
    const float s0 = INV_KEEP / l0;
    const float s1 = INV_KEEP / l1;

    const int rg = bq + w * 16 + (lane >> 2);
    float* C = out + ((size_t)b * NQ + rg) * DIM;
#pragma unroll
    for (int nf = 0; nf < 16; nf++) {
        const int c0 = nf * 8 + qr;
        *(float2*)(C + c0) = make_float2(O[nf][0] * s0, O[nf][1] * s0);
        *(float2*)(C + 8 * DIM + c0) = make_float2(O[nf][2] * s1, O[nf][3] * s1);
    }
}

// ---------------------------------------------------------------------------
extern "C" void kernel_launch(void* const* d_in, const int* in_sizes, int n_in,
                              void* d_out, int out_size) {
    const float* x1 = (const float*)d_in[0];
    const float* x2 = (const float*)d_in[1];
    float* out = (float*)d_out;

    cudaFuncSetAttribute(fused_attn, cudaFuncAttributeMaxDynamicSharedMemorySize, SMEM_BYTES);

    mask_kernel<<<(1u << 26) / 256, 256>>>();
    split_kernel<<<(BATCH * NQ * DIM) / 256, 256>>>(x1, x2);
    fused_attn<<<dim3(16, 16), 256, SMEM_BYTES>>>(out);
}